// round 16
// baseline (speedup 1.0000x reference)
#include <cuda_runtime.h>
#include <cuda_fp16.h>

// ---------------------------------------------------------------------------
// CausalEdgeAttention — fused persistent kernel, h stored fp16 (no GEMM1
// recompute in pass 2).
//   out = edge_attr + 0.5*((relu(ctx@W1+b1) * g) @ M + const8)
// R15 postmortem: fin was ~45-50us (1-block serial reduce) and out-phase
//   ~110us incl GEMM1 recompute. This round: (1) pass1 stores h fp16 via
//   smem-transposed coalesced chunks ([col][64-edge] layout, e>>6 indexing);
//   pass2 = GEMM2 only, 1 coalesced LDG.32 per edge-pair per col.
//   (2) two-level partials reduction (64 blocks then 1).
// ---------------------------------------------------------------------------

#define NSTATS 584
#define NFOLD  8
#define NBLK   (NSTATS + NFOLD)    // 592 = 4/SM * 148 SMs, one wave
#define PERB   896                 // edges per stats block = 14 chunks x 64
#define CHUNK  64
#define NCHUNK 14
#define NRED   64                  // level-1 reduction blocks

__device__ __align__(16) float g_U[256 * 8];
__device__ __align__(16) float g_V[256 * 8];
__device__ __align__(16) float g_M[256 * 8];
__device__ __align__(16) float g_Mg[256 * 8];
__device__ float g_c1[256];
__device__ float g_c2[256];
__device__ float g_c3[8];
__device__ __align__(16) float g_const8[8];
__device__ __align__(16) float g_part[NSTATS * 512];
__device__ __align__(16) float g_part2[NRED * 512];
__device__ int g_ctrA, g_ctrB, g_ctrC, g_ctrS, g_ctrS2, g_ctrR;
// h storage: [global_chunk = e>>6][col][tt] fp16, as uint (fp16x2 along tt)
__device__ __align__(16) unsigned g_h32[(size_t)NSTATS * NCHUNK * 8192];

// ---- packed f32x2 helpers -------------------------------------------------
__device__ __forceinline__ unsigned long long pk2(float lo, float hi) {
    unsigned long long r;
    asm("mov.b64 %0, {%1, %2};" : "=l"(r) : "f"(lo), "f"(hi));
    return r;
}
__device__ __forceinline__ void upk2(unsigned long long v, float& lo, float& hi) {
    asm("mov.b64 {%0, %1}, %2;" : "=f"(lo), "=f"(hi) : "l"(v));
}
#define FMA2(d, a, b, c) asm("fma.rn.f32x2 %0, %1, %2, %3;" : "=l"(d) : "l"(a), "l"(b), "l"(c))
#define ADD2(d, a, b)    asm("add.rn.f32x2 %0, %1, %2;" : "=l"(d) : "l"(a), "l"(b))

#define HALF2C 0x3F0000003F000000ULL   // (0.5f, 0.5f)

// ---- spin barrier helpers -------------------------------------------------
__device__ __forceinline__ void arrive(int* ctr) {
    __syncthreads();
    __threadfence();
    if (threadIdx.x == 0) atomicAdd(ctr, 1);
}
__device__ __forceinline__ void waitFor(int* ctr, int target) {
    if (threadIdx.x == 0) {
        while (atomicAdd(ctr, 0) < target) __nanosleep(128);
        __threadfence();
    }
    __syncthreads();
}

__global__ void kReset() {
    g_ctrA = 0; g_ctrB = 0; g_ctrC = 0; g_ctrS = 0; g_ctrS2 = 0; g_ctrR = 0;
}

// ---- fold stage bodies (unchanged, proven) --------------------------------
__device__ void foldA(int t, const float* __restrict__ Wo,
                      const float* __restrict__ Wp, const float* __restrict__ nb2,
                      const float* __restrict__ Wv, const float* __restrict__ bv) {
    if (t < 2048) {
        int i = t >> 3, d = t & 7;
        float a0 = 0.f, a1 = 0.f, a2 = 0.f, a3 = 0.f;
        for (int k = 0; k < 256; k += 4) {
            a0 = fmaf(Wo[i * 256 + k],     Wp[k * 8 + d],       a0);
            a1 = fmaf(Wo[i * 256 + k + 1], Wp[(k + 1) * 8 + d], a1);
            a2 = fmaf(Wo[i * 256 + k + 2], Wp[(k + 2) * 8 + d], a2);
            a3 = fmaf(Wo[i * 256 + k + 3], Wp[(k + 3) * 8 + d], a3);
        }
        g_U[t] = (a0 + a1) + (a2 + a3);
    } else if (t < 2304) {
        int i = t - 2048;
        float a0 = bv[i], a1 = 0.f, a2 = 0.f, a3 = 0.f;
        for (int k = 0; k < 256; k += 4) {
            a0 = fmaf(nb2[k],     Wv[k * 256 + i],       a0);
            a1 = fmaf(nb2[k + 1], Wv[(k + 1) * 256 + i], a1);
            a2 = fmaf(nb2[k + 2], Wv[(k + 2) * 256 + i], a2);
            a3 = fmaf(nb2[k + 3], Wv[(k + 3) * 256 + i], a3);
        }
        g_c1[i] = (a0 + a1) + (a2 + a3);
    }
}

__device__ void foldB(int t, const float* __restrict__ Wv,
                      const float* __restrict__ Wo, const float* __restrict__ bo) {
    if (t < 2048) {
        int i = t >> 3, d = t & 7;
        float a0 = 0.f, a1 = 0.f, a2 = 0.f, a3 = 0.f;
        for (int k = 0; k < 256; k += 4) {
            a0 = fmaf(Wv[i * 256 + k],     g_U[k * 8 + d],       a0);
            a1 = fmaf(Wv[i * 256 + k + 1], g_U[(k + 1) * 8 + d], a1);
            a2 = fmaf(Wv[i * 256 + k + 2], g_U[(k + 2) * 8 + d], a2);
            a3 = fmaf(Wv[i * 256 + k + 3], g_U[(k + 3) * 8 + d], a3);
        }
        g_V[t] = (a0 + a1) + (a2 + a3);
    } else if (t < 2304) {
        int i = t - 2048;
        float a0 = bo[i], a1 = 0.f, a2 = 0.f, a3 = 0.f;
        for (int k = 0; k < 256; k += 4) {
            a0 = fmaf(g_c1[k],     Wo[k * 256 + i],       a0);
            a1 = fmaf(g_c1[k + 1], Wo[(k + 1) * 256 + i], a1);
            a2 = fmaf(g_c1[k + 2], Wo[(k + 2) * 256 + i], a2);
            a3 = fmaf(g_c1[k + 3], Wo[(k + 3) * 256 + i], a3);
        }
        g_c2[i] = (a0 + a1) + (a2 + a3);
    }
}

__device__ void foldC(int t, const float* __restrict__ nW2,
                      const float* __restrict__ Wp, const float* __restrict__ bp) {
    if (t < 2048) {
        int i = t >> 3, d = t & 7;
        float a0 = 0.f, a1 = 0.f, a2 = 0.f, a3 = 0.f;
        for (int k = 0; k < 256; k += 4) {
            a0 = fmaf(nW2[i * 256 + k],     g_V[k * 8 + d],       a0);
            a1 = fmaf(nW2[i * 256 + k + 1], g_V[(k + 1) * 8 + d], a1);
            a2 = fmaf(nW2[i * 256 + k + 2], g_V[(k + 2) * 8 + d], a2);
            a3 = fmaf(nW2[i * 256 + k + 3], g_V[(k + 3) * 8 + d], a3);
        }
        g_M[t] = (a0 + a1) + (a2 + a3);
    } else if (t < 2056) {
        int d = t - 2048;
        float acc = bp[d];
        for (int k = 0; k < 256; k++) acc = fmaf(g_c2[k], Wp[k * 8 + d], acc);
        g_c3[d] = acc;
    }
}

// ---- the fused kernel -----------------------------------------------------
__global__ void __launch_bounds__(256, 4) kFused(
    const float* __restrict__ nf, const int* __restrict__ ei,
    const float* __restrict__ W1, const float* __restrict__ b1,
    const float* __restrict__ gamma, const float* __restrict__ beta,
    const float* __restrict__ Wo, const float* __restrict__ Wp,
    const float* __restrict__ nb2, const float* __restrict__ Wv,
    const float* __restrict__ bv, const float* __restrict__ bo,
    const float* __restrict__ nW2, const float* __restrict__ bp,
    const float* __restrict__ ea, float* __restrict__ out,
    int E, float invE) {
    __shared__ unsigned long long sCtx[2][CHUNK][4];  // 4KB staging
    __shared__ __align__(16) char sBuf[33792];        // pass1: hT[256][132B]
                                                      // pass2: sM[256][32B]+sC
    __shared__ float sh[256];                         // fin

    int tid = threadIdx.x;
    int bid = blockIdx.x;
    const ulonglong4* nfq = (const ulonglong4*)nf;

    if (bid < NSTATS) {
        // ---------------- phase 1: stats + fp16 h store ----------------------
        int j = tid;
        unsigned long long w01 = pk2(0.5f * W1[0 * 256 + j], 0.5f * W1[1 * 256 + j]);
        unsigned long long w23 = pk2(0.5f * W1[2 * 256 + j], 0.5f * W1[3 * 256 + j]);
        unsigned long long w45 = pk2(0.5f * W1[4 * 256 + j], 0.5f * W1[5 * 256 + j]);
        unsigned long long w67 = pk2(0.5f * W1[6 * 256 + j], 0.5f * W1[7 * 256 + j]);
        unsigned long long b2 = pk2(b1[j], 0.f);

        float s = 0.f, q = 0.f;
        int start = bid * PERB;
        int len = E - start;
        if (len < 0) len = 0;
        if (len > PERB) len = PERB;
        int nt = (len + CHUNK - 1) / CHUNK;

        // stage chunk 0
        if (tid < CHUNK && tid < len) {
            int e = start + tid;
            int a = ei[e], b = ei[E + e];
            ulonglong4 A = nfq[a], B = nfq[b];
            unsigned long long c0, c1, c2, c3;
            ADD2(c0, A.x, B.x); ADD2(c1, A.y, B.y);
            ADD2(c2, A.z, B.z); ADD2(c3, A.w, B.w);
            sCtx[0][tid][0] = c0; sCtx[0][tid][1] = c1;
            sCtx[0][tid][2] = c2; sCtx[0][tid][3] = c3;
        }

        for (int t = 0; t < nt; t++) {
            __syncthreads();   // stage(t) + previous flush complete
            if (t + 1 < nt && tid < CHUNK) {
                int e = start + (t + 1) * CHUNK + tid;
                if (e < start + len) {
                    int buf = (t + 1) & 1;
                    int a = ei[e], b = ei[E + e];
                    ulonglong4 A = nfq[a], B = nfq[b];
                    unsigned long long c0, c1, c2, c3;
                    ADD2(c0, A.x, B.x); ADD2(c1, A.y, B.y);
                    ADD2(c2, A.z, B.z); ADD2(c3, A.w, B.w);
                    sCtx[buf][tid][0] = c0; sCtx[buf][tid][1] = c1;
                    sCtx[buf][tid][2] = c2; sCtx[buf][tid][3] = c3;
                }
            }
            int buf = t & 1;
            int tlen = min(CHUNK, len - t * CHUNK);
            const ulonglong2* cb = (const ulonglong2*)&sCtx[buf][0][0];
            char* hrow = sBuf + tid * 132;
#pragma unroll 4
            for (int tt = 0; tt < tlen; tt++) {
                ulonglong2 c01 = cb[2 * tt];
                ulonglong2 c23 = cb[2 * tt + 1];
                unsigned long long acc;
                FMA2(acc, c01.x, w01, b2);
                FMA2(acc, c01.y, w23, acc);
                FMA2(acc, c23.x, w45, acc);
                FMA2(acc, c23.y, w67, acc);
                float lo, hi;
                upk2(acc, lo, hi);
                float h = fmaxf(lo + hi, 0.f);
                s += h;
                q = fmaf(h, h, q);
                *(__half*)(hrow + tt * 2) = __float2half_rn(h);
            }
            __syncthreads();   // hT complete
            // flush chunk t: [col][tt] coalesced, thread tid = its col row
            {
                unsigned gchunk = (unsigned)(bid * NCHUNK + t);
                unsigned* dst = g_h32 + (size_t)gchunk * 8192 + tid * 32;
                const char* src = sBuf + tid * 132;
#pragma unroll
                for (int i = 0; i < 8; i++) {
                    uint4 v;
                    v.x = *(const unsigned*)(src + i * 16 + 0);
                    v.y = *(const unsigned*)(src + i * 16 + 4);
                    v.z = *(const unsigned*)(src + i * 16 + 8);
                    v.w = *(const unsigned*)(src + i * 16 + 12);
                    ((uint4*)dst)[i] = v;
                }
            }
        }
        g_part[bid * 512 + tid] = s;
        g_part[bid * 512 + 256 + tid] = q;
        arrive(&g_ctrS);
    } else {
        // ---------------- fold chain on 8 blocks -----------------------------
        int t0 = (bid - NSTATS) * 256 + tid;
        foldA(t0, Wo, Wp, nb2, Wv, bv);
        foldA(t0 + 2048, Wo, Wp, nb2, Wv, bv);
        arrive(&g_ctrA);
        waitFor(&g_ctrA, NFOLD);
        foldB(t0, Wv, Wo, bo);
        foldB(t0 + 2048, Wv, Wo, bo);
        arrive(&g_ctrB);
        waitFor(&g_ctrB, NFOLD);
        foldC(t0, nW2, Wp, bp);
        foldC(t0 + 2048, nW2, Wp, bp);
        arrive(&g_ctrC);
    }

    // ---------------- level-1 stats reduction (blocks 0..63) -----------------
    if (bid < NRED) {
        waitFor(&g_ctrS, NSTATS);
        float s = 0.f, q = 0.f;
        for (int b = bid; b < NSTATS; b += NRED) {
            s += g_part[b * 512 + tid];
            q += g_part[b * 512 + 256 + tid];
        }
        g_part2[bid * 512 + tid] = s;
        g_part2[bid * 512 + 256 + tid] = q;
        arrive(&g_ctrS2);
    }

    // ---------------- BN finalize on block 0 ---------------------------------
    if (bid == 0) {
        waitFor(&g_ctrS2, NRED);
        waitFor(&g_ctrC, NFOLD);
        int j = tid;
        float s = 0.f, q = 0.f;
        for (int b = 0; b < NRED; b++) {
            s += g_part2[b * 512 + j];
            q += g_part2[b * 512 + 256 + j];
        }
        float mu = s * invE;
        float var = q * invE - mu * mu;
        float gg = gamma[j] * rsqrtf(var + 1e-5f);
        sh[j] = beta[j] - mu * gg;
#pragma unroll
        for (int d = 0; d < 8; d++) g_Mg[j * 8 + d] = gg * g_M[j * 8 + d];
        __syncthreads();
        int w = j >> 5, lane = j & 31;
        float acc = 0.f;
        for (int jj = lane; jj < 256; jj += 32) acc += sh[jj] * g_M[jj * 8 + w];
#pragma unroll
        for (int off = 16; off; off >>= 1)
            acc += __shfl_xor_sync(0xffffffffu, acc, off);
        if (lane == 0) g_const8[w] = acc + g_c3[w];
        arrive(&g_ctrR);
    }

    // ---------------- phase 2: GEMM2 only, stream stored h -------------------
    waitFor(&g_ctrR, 1);

    {
        // sBuf reuse: sM[256][32B] = g_Mg rows; const8 packed after
        ulonglong2* sM = (ulonglong2*)sBuf;
        sM[2 * tid] = ((const ulonglong2*)g_Mg)[2 * tid];
        sM[2 * tid + 1] = ((const ulonglong2*)g_Mg)[2 * tid + 1];
        if (tid < 4)
            ((unsigned long long*)(sBuf + 8192))[tid] =
                ((const unsigned long long*)g_const8)[tid];
    }
    __syncthreads();

    const ulonglong2* sM = (const ulonglong2*)sBuf;
    const unsigned long long* sC2 = (const unsigned long long*)(sBuf + 8192);
    const ulonglong4* eaq = (const ulonglong4*)ea;
    ulonglong4* outq = (ulonglong4*)out;
    const unsigned long long H2 = HALF2C;

    int totPairs = (E + 1) >> 1;
    int perP = (totPairs + NBLK - 1) / NBLK;
    int p0 = bid * perP;
    int p1 = min(p0 + perP, totPairs);

    for (int p = p0 + tid; p < p1; p += 256) {
        int e = 2 * p;
        const unsigned* hbase =
            g_h32 + (size_t)(e >> 6) * 8192 + ((e & 63) >> 1);

        unsigned long long yA0 = 0ull, yA1 = 0ull, yA2 = 0ull, yA3 = 0ull;
        unsigned long long yB0 = 0ull, yB1 = 0ull, yB2 = 0ull, yB3 = 0ull;

#pragma unroll 8
        for (int c = 0; c < 256; c++) {
            unsigned hw = __ldg(hbase + c * 32);
            __half2 hh = *reinterpret_cast<const __half2*>(&hw);
            float2 f = __half22float2(hh);
            unsigned long long hA2 = pk2(f.x, f.x);
            unsigned long long hB2 = pk2(f.y, f.y);
            ulonglong2 m0 = sM[2 * c];
            ulonglong2 m1 = sM[2 * c + 1];
            FMA2(yA0, hA2, m0.x, yA0);
            FMA2(yA1, hA2, m0.y, yA1);
            FMA2(yA2, hA2, m1.x, yA2);
            FMA2(yA3, hA2, m1.y, yA3);
            FMA2(yB0, hB2, m0.x, yB0);
            FMA2(yB1, hB2, m0.y, yB1);
            FMA2(yB2, hB2, m1.x, yB2);
            FMA2(yB3, hB2, m1.y, yB3);
        }

        {
            ulonglong4 ev = eaq[e];
            ulonglong4 ov;
            unsigned long long t;
            ADD2(t, yA0, sC2[0]); FMA2(ov.x, t, H2, ev.x);
            ADD2(t, yA1, sC2[1]); FMA2(ov.y, t, H2, ev.y);
            ADD2(t, yA2, sC2[2]); FMA2(ov.z, t, H2, ev.z);
            ADD2(t, yA3, sC2[3]); FMA2(ov.w, t, H2, ev.w);
            outq[e] = ov;
        }
        if (e + 1 < E) {
            ulonglong4 ev = eaq[e + 1];
            ulonglong4 ov;
            unsigned long long t;
            ADD2(t, yB0, sC2[0]); FMA2(ov.x, t, H2, ev.x);
            ADD2(t, yB1, sC2[1]); FMA2(ov.y, t, H2, ev.y);
            ADD2(t, yB2, sC2[2]); FMA2(ov.z, t, H2, ev.z);
            ADD2(t, yB3, sC2[3]); FMA2(ov.w, t, H2, ev.w);
            outq[e + 1] = ov;
        }
    }
}

// ---------------------------------------------------------------------------
extern "C" void kernel_launch(void* const* d_in, const int* in_sizes, int n_in,
                              void* d_out, int out_size) {
    const float* edge_attr = (const float*)d_in[0];
    const float* nf        = (const float*)d_in[1];
    const int*   ei        = (const int*)d_in[2];
    // d_in[3..8]: edge-encoder params (dead code in reference)
    const float* nW1   = (const float*)d_in[9];
    const float* nb1   = (const float*)d_in[10];
    const float* ngam  = (const float*)d_in[11];
    const float* nbet  = (const float*)d_in[12];
    const float* nW2   = (const float*)d_in[13];
    const float* nb2   = (const float*)d_in[14];
    const float* Wv    = (const float*)d_in[15];
    const float* bv    = (const float*)d_in[16];
    const float* Wo    = (const float*)d_in[17];
    const float* bo    = (const float*)d_in[18];
    const float* Wp    = (const float*)d_in[19];
    const float* bp    = (const float*)d_in[20];
    float* out = (float*)d_out;

    int E = in_sizes[0] / 8;

    kReset<<<1, 32>>>();
    kFused<<<NBLK, 256>>>(nf, ei, nW1, nb1, ngam, nbet,
                          Wo, Wp, nb2, Wv, bv, bo, nW2, bp,
                          edge_attr, out, E, 1.0f / (float)E);
}